// round 9
// baseline (speedup 1.0000x reference)
#include <cuda_runtime.h>
#include <cuda_bf16.h>

// Problem constants (fixed by the dataset)
#define NN   2048   // nodes
#define ZD   64     // z_dim
#define HID  64     // hidden
#define TJ   256    // j-columns per block (== blockDim.x)
#define RI   8      // i-rows per block (packed accumulators: 2 regs each)
#define NPB  4      // nodes per block in stage 1
#define KH   32     // k's per smem-staged half
#define QH   (KH/4) // quads per half = 8

// Scratch (allocation-free rule: __device__ globals)
__device__ float g_PI [NN * HID];   // pi[n][h] = z@W1[:ZD] + b1  (row-major)
__device__ float g_PJ4[HID * NN];   // pj^T quad-interleaved: [(h>>2)][n][h&3]
__device__ float g_A  [NN];         // a_i = sum_k pi[i,k] * w2[k]
__device__ float g_B  [NN];         // b_j = sum_k pj[j,k] * w2[k]

// sm_103a packed fp32 ops (FFMA2-class, fma pipe)
#define F32X2_ADD(d, a, b) \
    asm("add.rn.f32x2 %0, %1, %2;" : "=l"(d) : "l"(a), "l"(b))
#define F32X2_FMA(d, a, b, c) \
    asm("fma.rn.f32x2 %0, %1, %2, %3;" : "=l"(d) : "l"(a), "l"(b), "l"(c))

// ---------------------------------------------------------------------------
// Stage 1: projections + rank-1 terms. NPB nodes per block; W1 L1-resident
// after the first node.
//   half 0 (t<64):  pi[n][h] = z[n]@W1[:ZD,h] + b1[h]  -> g_PI
//   half 1 (t>=64): pj[n][h] = z[n]@W1[ZD:,h]          -> g_PJ4 (quad-interleaved)
// Fused: a[n] = sum_h pi*w2, b[n] = sum_h pj*w2 via shuffle reduce.
// ---------------------------------------------------------------------------
__global__ void edge_proj_kernel(const float* __restrict__ z,
                                 const float* __restrict__ W1,
                                 const float* __restrict__ b1,
                                 const float* __restrict__ W2) {
    __shared__ float zs[ZD];
    __shared__ float red[4];
    const int t    = threadIdx.x;            // 0..127
    const int half = t >> 6;
    const int h    = t & 63;
    const float* w  = W1 + (half * ZD) * HID + h;   // column h of the right half
    const float b1v = b1[h];
    const float w2v = W2[h];

    for (int rep = 0; rep < NPB; rep++) {
        const int n = blockIdx.x * NPB + rep;
        if (t < ZD) zs[t] = z[n * ZD + t];
        __syncthreads();

        float acc = 0.f;
        #pragma unroll
        for (int d = 0; d < ZD; d++)
            acc = fmaf(zs[d], w[d * HID], acc);      // W1 loads: L1 hits after rep 0

        const float val = (half == 0) ? (acc + b1v) : acc;
        if (half == 0) g_PI [n * HID + h] = val;
        else           g_PJ4[(h >> 2) * (4 * NN) + 4 * n + (h & 3)] = val;

        // fused a/b reduction
        float v = val * w2v;
        #pragma unroll
        for (int off = 16; off; off >>= 1)
            v += __shfl_down_sync(0xffffffffu, v, off);
        if ((t & 31) == 0) red[t >> 5] = v;
        __syncthreads();
        if (t == 0)  g_A[n] = red[0] + red[1];
        if (t == 64) g_B[n] = red[2] + red[3];
        __syncthreads();   // protect zs/red before next rep
    }
}

// ---------------------------------------------------------------------------
// Stage 2: pairwise core, relu removed via relu(x) = (x+|x|)/2:
//   logit = 0.5*(a_i + b_j + sum_k |pi+pj|*w2_k) + b2
// pj for the block's 256 j's is staged through smem in two 32KB halves
// (coalesced cooperative fill); steady loop has NO global loads.
// RI=8 + __launch_bounds__(256,4): <=64 regs -> 4 blocks/SM (32 warps) to
// cover the 29-cyc LDS latency chains that capped issue at 59% with RI=16.
// Inner per 2 k's: add.rn.f32x2 (fma), 64-bit abs (2 LOP3, alu), fma.rn.f32x2.
// ---------------------------------------------------------------------------
__global__ void __launch_bounds__(TJ, 4)
edge_pair_kernel(const float* __restrict__ W2,
                 const float* __restrict__ b2,
                 float* __restrict__ out) {
    __shared__ __align__(16) float4 s_pj[QH * TJ];  // 32KB: one k-half, quad layout
    __shared__ __align__(16) float  s_pi[RI * HID]; // 2KB
    __shared__ __align__(16) float  s_w2[HID];
    __shared__ float s_lin[RI];

    const int t  = threadIdx.x;
    const int j0 = blockIdx.x * TJ;
    const int i0 = blockIdx.y * RI;

    #pragma unroll
    for (int idx = t; idx < RI * HID; idx += TJ)
        s_pi[idx] = g_PI[i0 * HID + idx];
    if (t < HID) s_w2[t] = W2[t];
    if (t < RI)  s_lin[t] = g_A[i0 + t];

    unsigned long long acc[RI];
    #pragma unroll
    for (int i = 0; i < RI; i++) acc[i] = 0ULL;

    const unsigned long long ABSM = 0x7fffffff7fffffffULL;

    #pragma unroll 1
    for (int hf = 0; hf < 2; hf++) {
        if (hf) __syncthreads();   // all reads of previous half complete

        // Cooperative fill: quad Q = hf*QH + q lives at g_PJ4[Q*4*NN + 4*j].
        // Per quad: 4KB contiguous span -> fully coalesced LDG.128/STS.128.
        {
            const float4* src = reinterpret_cast<const float4*>(
                                    &g_PJ4[(hf * QH) * (4 * NN) + 4 * j0]);
            #pragma unroll
            for (int q = 0; q < QH; q++)
                s_pj[q * TJ + t] = src[q * NN + t];   // NN float4s between quads
        }
        __syncthreads();   // (also covers s_pi/s_w2/s_lin fills when hf==0)

        #pragma unroll
        for (int c = 0; c < KH / 8; c++) {            // 4 chunks of 8 k's
            // This thread's pj chunk: quads 2c, 2c+1 -> 2 LDS.128, 4 k-pairs
            const ulonglong2 pA = *reinterpret_cast<const ulonglong2*>(
                                      &s_pj[(2 * c + 0) * TJ + t]);
            const ulonglong2 pB = *reinterpret_cast<const ulonglong2*>(
                                      &s_pj[(2 * c + 1) * TJ + t]);
            // Matching w2 pairs (broadcast LDS.128 x2)
            const ulonglong2* w2q = reinterpret_cast<const ulonglong2*>(
                                        &s_w2[hf * KH + 8 * c]);
            const ulonglong2 wA = w2q[0];
            const ulonglong2 wB = w2q[1];

            #pragma unroll
            for (int i = 0; i < RI; i++) {
                const ulonglong2* pp = reinterpret_cast<const ulonglong2*>(
                                           &s_pi[i * HID + hf * KH + 8 * c]);
                const ulonglong2 a0 = pp[0];          // broadcast LDS.128
                const ulonglong2 a1 = pp[1];
                unsigned long long s;
                F32X2_ADD(s, a0.x, pA.x); s &= ABSM; F32X2_FMA(acc[i], s, wA.x, acc[i]);
                F32X2_ADD(s, a0.y, pA.y); s &= ABSM; F32X2_FMA(acc[i], s, wA.y, acc[i]);
                F32X2_ADD(s, a1.x, pB.x); s &= ABSM; F32X2_FMA(acc[i], s, wB.x, acc[i]);
                F32X2_ADD(s, a1.y, pB.y); s &= ABSM; F32X2_FMA(acc[i], s, wB.y, acc[i]);
            }
        }
    }

    const float b2v = b2[0];
    const float bj  = g_B[j0 + t];
    #pragma unroll
    for (int i = 0; i < RI; i++) {
        const float lo = __uint_as_float((unsigned)(acc[i] & 0xffffffffULL));
        const float hi = __uint_as_float((unsigned)(acc[i] >> 32));
        const float x  = fmaf(0.5f, s_lin[i] + bj + (lo + hi), b2v);
        out[(i0 + i) * NN + j0 + t] = 1.0f / (1.0f + __expf(-x));
    }
}

// ---------------------------------------------------------------------------
// Inputs per metadata order: z, W1, b1, W2, b2. Output: float32 [2048*2048].
// Graph-capturable: two launches, no sync, no allocation.
// ---------------------------------------------------------------------------
extern "C" void kernel_launch(void* const* d_in, const int* in_sizes, int n_in,
                              void* d_out, int out_size) {
    const float* z  = (const float*)d_in[0];
    const float* W1 = (const float*)d_in[1];
    const float* b1 = (const float*)d_in[2];
    const float* W2 = (const float*)d_in[3];
    const float* b2 = (const float*)d_in[4];
    float* out = (float*)d_out;

    edge_proj_kernel<<<NN / NPB, 128>>>(z, W1, b1, W2);

    dim3 grid(NN / TJ, NN / RI);
    edge_pair_kernel<<<grid, TJ>>>(W2, b2, out);
}

// round 10
// speedup vs baseline: 1.0391x; 1.0391x over previous
#include <cuda_runtime.h>
#include <cuda_bf16.h>

// Problem constants (fixed by the dataset)
#define NN   2048   // nodes
#define ZD   64     // z_dim
#define HID  64     // hidden
#define TJB  256    // j-columns per block
#define TB   128    // threads per block (each owns 2 j's: t and t+128)
#define RI   8      // i-rows per block (packed accumulators)
#define NPB  4      // nodes per block in stage 1
#define KH   32     // k's per smem-staged half
#define QH   (KH/4) // quads per half = 8

// Scratch (allocation-free rule: __device__ globals)
__device__ float g_PI [NN * HID];   // pi[n][h] = z@W1[:ZD] + b1  (row-major)
__device__ float g_PJ4[HID * NN];   // pj^T quad-interleaved: [(h>>2)][n][h&3]
__device__ float g_A  [NN];         // a_i = sum_k pi[i,k] * w2[k]
__device__ float g_B  [NN];         // b_j = sum_k pj[j,k] * w2[k]

// sm_103a packed fp32 ops (FFMA2-class, fma pipe)
#define F32X2_ADD(d, a, b) \
    asm("add.rn.f32x2 %0, %1, %2;" : "=l"(d) : "l"(a), "l"(b))
#define F32X2_FMA(d, a, b, c) \
    asm("fma.rn.f32x2 %0, %1, %2, %3;" : "=l"(d) : "l"(a), "l"(b), "l"(c))

// ---------------------------------------------------------------------------
// Stage 1: projections + rank-1 terms (unchanged from R8).
// ---------------------------------------------------------------------------
__global__ void edge_proj_kernel(const float* __restrict__ z,
                                 const float* __restrict__ W1,
                                 const float* __restrict__ b1,
                                 const float* __restrict__ W2) {
    __shared__ float zs[ZD];
    __shared__ float red[4];
    const int t    = threadIdx.x;            // 0..127
    const int half = t >> 6;
    const int h    = t & 63;
    const float* w  = W1 + (half * ZD) * HID + h;
    const float b1v = b1[h];
    const float w2v = W2[h];

    for (int rep = 0; rep < NPB; rep++) {
        const int n = blockIdx.x * NPB + rep;
        if (t < ZD) zs[t] = z[n * ZD + t];
        __syncthreads();

        float acc = 0.f;
        #pragma unroll
        for (int d = 0; d < ZD; d++)
            acc = fmaf(zs[d], w[d * HID], acc);

        const float val = (half == 0) ? (acc + b1v) : acc;
        if (half == 0) g_PI [n * HID + h] = val;
        else           g_PJ4[(h >> 2) * (4 * NN) + 4 * n + (h & 3)] = val;

        float v = val * w2v;
        #pragma unroll
        for (int off = 16; off; off >>= 1)
            v += __shfl_down_sync(0xffffffffu, v, off);
        if ((t & 31) == 0) red[t >> 5] = v;
        __syncthreads();
        if (t == 0)  g_A[n] = red[0] + red[1];
        if (t == 64) g_B[n] = red[2] + red[3];
        __syncthreads();
    }
}

// ---------------------------------------------------------------------------
// Stage 2: pairwise core. relu(x) = (x+|x|)/2 ->
//   logit = 0.5*(a_i + b_j + sum_k |pi+pj|*w2_k) + b2
// LDS-crossbar-bound fix (R9 evidence): register-block j. Each thread owns
// TWO j columns (t, t+128), so the expensive pi-broadcast LDS stream
// amortizes over 2x the pairs: 0.0215 -> 0.0127 wavefronts/pair-k.
// pj staged via smem in two 32KB halves; steady loop has no global loads.
// ---------------------------------------------------------------------------
__global__ void __launch_bounds__(TB, 6)
edge_pair_kernel(const float* __restrict__ W2,
                 const float* __restrict__ b2,
                 float* __restrict__ out) {
    __shared__ __align__(16) float4 s_pj[QH * TJB]; // 32KB: one k-half, quad layout
    __shared__ __align__(16) float  s_pi[RI * HID]; // 2KB
    __shared__ __align__(16) float  s_w2[HID];
    __shared__ float s_lin[RI];

    const int t  = threadIdx.x;                     // 0..127
    const int j0 = blockIdx.x * TJB;
    const int i0 = blockIdx.y * RI;

    #pragma unroll
    for (int idx = t; idx < RI * HID; idx += TB)
        s_pi[idx] = g_PI[i0 * HID + idx];
    if (t < HID) s_w2[t] = W2[t];
    if (t < RI)  s_lin[t] = g_A[i0 + t];

    // acc[i][jr]: packed f32x2 accumulators for (i0+i, j0+t) and (i0+i, j0+t+128)
    unsigned long long acc0[RI], acc1[RI];
    #pragma unroll
    for (int i = 0; i < RI; i++) { acc0[i] = 0ULL; acc1[i] = 0ULL; }

    const unsigned long long ABSM = 0x7fffffff7fffffffULL;

    #pragma unroll 1
    for (int hf = 0; hf < 2; hf++) {
        if (hf) __syncthreads();   // all reads of previous half complete

        // Cooperative fill: quad Q = hf*QH + q of j-range [j0, j0+256).
        // Each quad's source span is 4KB contiguous -> coalesced LDG.128.
        {
            const float4* src = reinterpret_cast<const float4*>(
                                    &g_PJ4[(hf * QH) * (4 * NN) + 4 * j0]);
            #pragma unroll
            for (int q = 0; q < QH; q++) {
                s_pj[q * TJB + t      ] = src[q * NN + t      ];
                s_pj[q * TJB + t + TB ] = src[q * NN + t + TB ];
            }
        }
        __syncthreads();   // (also covers s_pi/s_w2/s_lin fills when hf==0)

        #pragma unroll
        for (int c = 0; c < KH / 8; c++) {            // 4 chunks of 8 k's
            // pj chunk for this thread's two j's (spread LDS.128 x4)
            const ulonglong2 pA0 = *reinterpret_cast<const ulonglong2*>(
                                       &s_pj[(2 * c + 0) * TJB + t]);
            const ulonglong2 pB0 = *reinterpret_cast<const ulonglong2*>(
                                       &s_pj[(2 * c + 1) * TJB + t]);
            const ulonglong2 pA1 = *reinterpret_cast<const ulonglong2*>(
                                       &s_pj[(2 * c + 0) * TJB + t + TB]);
            const ulonglong2 pB1 = *reinterpret_cast<const ulonglong2*>(
                                       &s_pj[(2 * c + 1) * TJB + t + TB]);
            // w2 pairs (broadcast LDS.128 x2)
            const ulonglong2* w2q = reinterpret_cast<const ulonglong2*>(
                                        &s_w2[hf * KH + 8 * c]);
            const ulonglong2 wA = w2q[0];
            const ulonglong2 wB = w2q[1];

            #pragma unroll
            for (int i = 0; i < RI; i++) {
                const ulonglong2* pp = reinterpret_cast<const ulonglong2*>(
                                           &s_pi[i * HID + hf * KH + 8 * c]);
                const ulonglong2 a0 = pp[0];          // broadcast LDS.128
                const ulonglong2 a1 = pp[1];          // reused for BOTH j's
                unsigned long long s;
                // jr = 0 (j = j0 + t)
                F32X2_ADD(s, a0.x, pA0.x); s &= ABSM; F32X2_FMA(acc0[i], s, wA.x, acc0[i]);
                F32X2_ADD(s, a0.y, pA0.y); s &= ABSM; F32X2_FMA(acc0[i], s, wA.y, acc0[i]);
                F32X2_ADD(s, a1.x, pB0.x); s &= ABSM; F32X2_FMA(acc0[i], s, wB.x, acc0[i]);
                F32X2_ADD(s, a1.y, pB0.y); s &= ABSM; F32X2_FMA(acc0[i], s, wB.y, acc0[i]);
                // jr = 1 (j = j0 + t + 128)
                F32X2_ADD(s, a0.x, pA1.x); s &= ABSM; F32X2_FMA(acc1[i], s, wA.x, acc1[i]);
                F32X2_ADD(s, a0.y, pA1.y); s &= ABSM; F32X2_FMA(acc1[i], s, wA.y, acc1[i]);
                F32X2_ADD(s, a1.x, pB1.x); s &= ABSM; F32X2_FMA(acc1[i], s, wB.x, acc1[i]);
                F32X2_ADD(s, a1.y, pB1.y); s &= ABSM; F32X2_FMA(acc1[i], s, wB.y, acc1[i]);
            }
        }
    }

    const float b2v = b2[0];
    const float bj0 = g_B[j0 + t];
    const float bj1 = g_B[j0 + t + TB];
    #pragma unroll
    for (int i = 0; i < RI; i++) {
        const float lo0 = __uint_as_float((unsigned)(acc0[i] & 0xffffffffULL));
        const float hi0 = __uint_as_float((unsigned)(acc0[i] >> 32));
        const float x0  = fmaf(0.5f, s_lin[i] + bj0 + (lo0 + hi0), b2v);
        out[(i0 + i) * NN + j0 + t     ] = 1.0f / (1.0f + __expf(-x0));
        const float lo1 = __uint_as_float((unsigned)(acc1[i] & 0xffffffffULL));
        const float hi1 = __uint_as_float((unsigned)(acc1[i] >> 32));
        const float x1  = fmaf(0.5f, s_lin[i] + bj1 + (lo1 + hi1), b2v);
        out[(i0 + i) * NN + j0 + t + TB] = 1.0f / (1.0f + __expf(-x1));
    }
}

// ---------------------------------------------------------------------------
// Inputs per metadata order: z, W1, b1, W2, b2. Output: float32 [2048*2048].
// Graph-capturable: two launches, no sync, no allocation.
// ---------------------------------------------------------------------------
extern "C" void kernel_launch(void* const* d_in, const int* in_sizes, int n_in,
                              void* d_out, int out_size) {
    const float* z  = (const float*)d_in[0];
    const float* W1 = (const float*)d_in[1];
    const float* b1 = (const float*)d_in[2];
    const float* W2 = (const float*)d_in[3];
    const float* b2 = (const float*)d_in[4];
    float* out = (float*)d_out;

    edge_proj_kernel<<<NN / NPB, 128>>>(z, W1, b1, W2);

    dim3 grid(NN / TJB, NN / RI);
    edge_pair_kernel<<<grid, TB>>>(W2, b2, out);
}

// round 11
// speedup vs baseline: 1.1324x; 1.0898x over previous
#include <cuda_runtime.h>
#include <cuda_bf16.h>

// Problem constants (fixed by the dataset)
#define NN   2048   // nodes
#define ZD   64     // z_dim
#define HID  64     // hidden
#define TJB  256    // j-columns per block
#define TB   128    // threads per block (each owns 2 j's: t and t+128)
#define RI   8      // i-rows per block (packed accumulators)
#define NPB  4      // nodes per block in stage 1
#define KH   32     // k's per smem-staged half
#define QH   (KH/4) // quads per half = 8

// Scratch (allocation-free rule: __device__ globals)
__device__ float g_PI [NN * HID];   // pi[n][h] = z@W1[:ZD] + b1  (row-major)
__device__ float g_PJ4[HID * NN];   // pj^T quad-interleaved: [(h>>2)][n][h&3]
__device__ float g_A  [NN];         // a_i = sum_k pi[i,k] * w2[k]
__device__ float g_B  [NN];         // b_j = sum_k pj[j,k] * w2[k]

// sm_103a packed fp32 ops (FFMA2-class, fma pipe)
#define F32X2_ADD(d, a, b) \
    asm("add.rn.f32x2 %0, %1, %2;" : "=l"(d) : "l"(a), "l"(b))
#define F32X2_FMA(d, a, b, c) \
    asm("fma.rn.f32x2 %0, %1, %2, %3;" : "=l"(d) : "l"(a), "l"(b), "l"(c))

// ---------------------------------------------------------------------------
// Stage 1: projections + rank-1 terms (unchanged; ~2-4us, W1 L1-resident).
// ---------------------------------------------------------------------------
__global__ void edge_proj_kernel(const float* __restrict__ z,
                                 const float* __restrict__ W1,
                                 const float* __restrict__ b1,
                                 const float* __restrict__ W2) {
    __shared__ float zs[ZD];
    __shared__ float red[4];
    const int t    = threadIdx.x;            // 0..127
    const int half = t >> 6;
    const int h    = t & 63;
    const float* w  = W1 + (half * ZD) * HID + h;
    const float b1v = b1[h];
    const float w2v = W2[h];

    for (int rep = 0; rep < NPB; rep++) {
        const int n = blockIdx.x * NPB + rep;
        if (t < ZD) zs[t] = z[n * ZD + t];
        __syncthreads();

        float acc = 0.f;
        #pragma unroll
        for (int d = 0; d < ZD; d++)
            acc = fmaf(zs[d], w[d * HID], acc);

        const float val = (half == 0) ? (acc + b1v) : acc;
        if (half == 0) g_PI [n * HID + h] = val;
        else           g_PJ4[(h >> 2) * (4 * NN) + 4 * n + (h & 3)] = val;

        float v = val * w2v;
        #pragma unroll
        for (int off = 16; off; off >>= 1)
            v += __shfl_down_sync(0xffffffffu, v, off);
        if ((t & 31) == 0) red[t >> 5] = v;
        __syncthreads();
        if (t == 0)  g_A[n] = red[0] + red[1];
        if (t == 64) g_B[n] = red[2] + red[3];
        __syncthreads();
    }
}

// ---------------------------------------------------------------------------
// Stage 2: pairwise core. relu(x) = (x+|x|)/2 ->
//   logit = 0.5*(a_i + b_j + sum_k |pi+pj|*w2_k) + b2
// R11: inner chunk rewritten as 8 explicitly-independent chains per i
// (4 k-pair halves x 2 jr), phase-ordered ADDs -> LOP3s -> FMAs so every
// cross-pipe RAW (5 cyc) has >=8 issue slots of distance. All chunk LDS
// (w2 + 4 pj) hoisted above the i-loop.
// ---------------------------------------------------------------------------
__global__ void __launch_bounds__(TB, 6)
edge_pair_kernel(const float* __restrict__ W2,
                 const float* __restrict__ b2,
                 float* __restrict__ out) {
    __shared__ __align__(16) float4 s_pj[QH * TJB]; // 32KB: one k-half, quad layout
    __shared__ __align__(16) float  s_pi[RI * HID]; // 2KB
    __shared__ __align__(16) float  s_w2[HID];
    __shared__ float s_lin[RI];

    const int t  = threadIdx.x;                     // 0..127
    const int j0 = blockIdx.x * TJB;
    const int i0 = blockIdx.y * RI;

    #pragma unroll
    for (int idx = t; idx < RI * HID; idx += TB)
        s_pi[idx] = g_PI[i0 * HID + idx];
    if (t < HID) s_w2[t] = W2[t];
    if (t < RI)  s_lin[t] = g_A[i0 + t];

    unsigned long long acc0[RI], acc1[RI];
    #pragma unroll
    for (int i = 0; i < RI; i++) { acc0[i] = 0ULL; acc1[i] = 0ULL; }

    const unsigned long long ABSM = 0x7fffffff7fffffffULL;

    #pragma unroll 1
    for (int hf = 0; hf < 2; hf++) {
        if (hf) __syncthreads();   // all reads of previous half complete

        // Cooperative fill: quad Q = hf*QH + q of j-range [j0, j0+256).
        {
            const float4* src = reinterpret_cast<const float4*>(
                                    &g_PJ4[(hf * QH) * (4 * NN) + 4 * j0]);
            #pragma unroll
            for (int q = 0; q < QH; q++) {
                s_pj[q * TJB + t      ] = src[q * NN + t      ];
                s_pj[q * TJB + t + TB ] = src[q * NN + t + TB ];
            }
        }
        __syncthreads();   // (also covers s_pi/s_w2/s_lin fills when hf==0)

        #pragma unroll
        for (int c = 0; c < KH / 8; c++) {            // 4 chunks of 8 k's
            // ---- hoisted chunk loads (6 LDS.128) ----
            const ulonglong2 pA0 = *reinterpret_cast<const ulonglong2*>(
                                       &s_pj[(2 * c + 0) * TJB + t]);
            const ulonglong2 pB0 = *reinterpret_cast<const ulonglong2*>(
                                       &s_pj[(2 * c + 1) * TJB + t]);
            const ulonglong2 pA1 = *reinterpret_cast<const ulonglong2*>(
                                       &s_pj[(2 * c + 0) * TJB + t + TB]);
            const ulonglong2 pB1 = *reinterpret_cast<const ulonglong2*>(
                                       &s_pj[(2 * c + 1) * TJB + t + TB]);
            const ulonglong2* w2q = reinterpret_cast<const ulonglong2*>(
                                        &s_w2[hf * KH + 8 * c]);
            const ulonglong2 wA = w2q[0];
            const ulonglong2 wB = w2q[1];

            #pragma unroll
            for (int i = 0; i < RI; i++) {
                const ulonglong2* pp = reinterpret_cast<const ulonglong2*>(
                                           &s_pi[i * HID + hf * KH + 8 * c]);
                const ulonglong2 a0 = pp[0];          // broadcast LDS.128
                const ulonglong2 a1 = pp[1];          // shared by both jr's

                // Phase 1: 8 independent packed ADDs
                unsigned long long s00, s01, s02, s03, s10, s11, s12, s13;
                F32X2_ADD(s00, a0.x, pA0.x);
                F32X2_ADD(s10, a0.x, pA1.x);
                F32X2_ADD(s01, a0.y, pA0.y);
                F32X2_ADD(s11, a0.y, pA1.y);
                F32X2_ADD(s02, a1.x, pB0.x);
                F32X2_ADD(s12, a1.x, pB1.x);
                F32X2_ADD(s03, a1.y, pB0.y);
                F32X2_ADD(s13, a1.y, pB1.y);
                // Phase 2: abs (independent LOP3 pairs, alu pipe)
                s00 &= ABSM; s10 &= ABSM;
                s01 &= ABSM; s11 &= ABSM;
                s02 &= ABSM; s12 &= ABSM;
                s03 &= ABSM; s13 &= ABSM;
                // Phase 3: FMAs; acc0/acc1 chains interleaved (dep dist 2)
                F32X2_FMA(acc0[i], s00, wA.x, acc0[i]);
                F32X2_FMA(acc1[i], s10, wA.x, acc1[i]);
                F32X2_FMA(acc0[i], s01, wA.y, acc0[i]);
                F32X2_FMA(acc1[i], s11, wA.y, acc1[i]);
                F32X2_FMA(acc0[i], s02, wB.x, acc0[i]);
                F32X2_FMA(acc1[i], s12, wB.x, acc1[i]);
                F32X2_FMA(acc0[i], s03, wB.y, acc0[i]);
                F32X2_FMA(acc1[i], s13, wB.y, acc1[i]);
            }
        }
    }

    const float b2v = b2[0];
    const float bj0 = g_B[j0 + t];
    const float bj1 = g_B[j0 + t + TB];
    #pragma unroll
    for (int i = 0; i < RI; i++) {
        const float lo0 = __uint_as_float((unsigned)(acc0[i] & 0xffffffffULL));
        const float hi0 = __uint_as_float((unsigned)(acc0[i] >> 32));
        const float x0  = fmaf(0.5f, s_lin[i] + bj0 + (lo0 + hi0), b2v);
        out[(i0 + i) * NN + j0 + t     ] = 1.0f / (1.0f + __expf(-x0));
        const float lo1 = __uint_as_float((unsigned)(acc1[i] & 0xffffffffULL));
        const float hi1 = __uint_as_float((unsigned)(acc1[i] >> 32));
        const float x1  = fmaf(0.5f, s_lin[i] + bj1 + (lo1 + hi1), b2v);
        out[(i0 + i) * NN + j0 + t + TB] = 1.0f / (1.0f + __expf(-x1));
    }
}

// ---------------------------------------------------------------------------
// Inputs per metadata order: z, W1, b1, W2, b2. Output: float32 [2048*2048].
// Graph-capturable: two launches, no sync, no allocation.
// ---------------------------------------------------------------------------
extern "C" void kernel_launch(void* const* d_in, const int* in_sizes, int n_in,
                              void* d_out, int out_size) {
    const float* z  = (const float*)d_in[0];
    const float* W1 = (const float*)d_in[1];
    const float* b1 = (const float*)d_in[2];
    const float* W2 = (const float*)d_in[3];
    const float* b2 = (const float*)d_in[4];
    float* out = (float*)d_out;

    edge_proj_kernel<<<NN / NPB, 128>>>(z, W1, b1, W2);

    dim3 grid(NN / TJB, NN / RI);
    edge_pair_kernel<<<grid, TB>>>(W2, b2, out);
}